// round 1
// baseline (speedup 1.0000x reference)
#include <cuda_runtime.h>
#include <math.h>

// Problem constants
#define NB 32
#define CD 1024
#define BD 1024
#define EPSF 1e-12f

// Scratch (allocation-free rule: __device__ globals)
__device__ float g_K [NB * CD * BD];   // 128 MB
__device__ float g_Q [NB * CD * BD];   // 128 MB
__device__ float g_Y [NB * BD * BD];   // 128 MB (Y, then SM in place)
__device__ float g_DK2[NB * BD];
__device__ float g_DQ2[NB * BD];

// ---------------------------------------------------------------------------
// Tiled SGEMM: 128x128 tile, BK=8, 256 threads, 8x8 per-thread microtile.
// TRANSA=false: A is [M,K] row-major.  TRANSA=true: A is stored [K,M] row-major
// (used for Y = Q^T K where Q is [C,B]).
// EPI=0: out = acc (+ bias[row] if bias != nullptr)
// EPI=1: out = acc * rsqrt(max(rs[n*BD+row] * cs[n*BD+col], EPS))
// ---------------------------------------------------------------------------
#define BM 128
#define BN 128
#define BK 8
#define TM 8
#define TN 8

template <bool TRANSA, int EPI>
__global__ __launch_bounds__(256)
void gemm_kernel(const float* __restrict__ Aall,
                 const float* __restrict__ Ball,
                 float* __restrict__ Call,
                 int M, int N, int K,
                 size_t sA, size_t sB, size_t sC,
                 const float* __restrict__ bias,
                 const float* __restrict__ rs,
                 const float* __restrict__ cs)
{
    const int n = blockIdx.z;
    const float* A = Aall + (size_t)n * sA;
    const float* B = Ball + (size_t)n * sB;
    float*       C = Call + (size_t)n * sC;

    const int bm = blockIdx.y * BM;
    const int bn = blockIdx.x * BN;

    __shared__ __align__(16) float As[BK][BM];
    __shared__ __align__(16) float Bs[BK][BN];

    const int tid = threadIdx.x;
    const int tx  = tid & 15;        // 0..15  -> col group
    const int ty  = tid >> 4;        // 0..15  -> row group

    // B-tile (and trans-A-tile) loader coords: 8 rows x 32 float4 cols
    const int lRow = tid >> 5;            // 0..7
    const int lCol = (tid & 31) << 2;     // 0,4,...,124
    // non-trans A-tile loader coords: 128 rows x 2 float4 cols
    const int aRow = tid >> 1;            // 0..127
    const int aCol = (tid & 1) << 2;      // 0 or 4

    float acc[TM][TN] = {};
    float ra[TM], rb[TN];

    for (int k0 = 0; k0 < K; k0 += BK) {
        if (!TRANSA) {
            float4 v = *(const float4*)&A[(size_t)(bm + aRow) * K + k0 + aCol];
            As[aCol + 0][aRow] = v.x;
            As[aCol + 1][aRow] = v.y;
            As[aCol + 2][aRow] = v.z;
            As[aCol + 3][aRow] = v.w;
        } else {
            // A stored [K, M]: As[k][m] = A[(k0+k)*M + bm+m]
            float4 v = *(const float4*)&A[(size_t)(k0 + lRow) * M + bm + lCol];
            *(float4*)&As[lRow][lCol] = v;
        }
        {
            float4 v = *(const float4*)&B[(size_t)(k0 + lRow) * N + bn + lCol];
            *(float4*)&Bs[lRow][lCol] = v;
        }
        __syncthreads();

        #pragma unroll
        for (int k = 0; k < BK; k++) {
            *(float4*)&ra[0] = *(const float4*)&As[k][ty * TM];
            *(float4*)&ra[4] = *(const float4*)&As[k][ty * TM + 4];
            *(float4*)&rb[0] = *(const float4*)&Bs[k][tx * TN];
            *(float4*)&rb[4] = *(const float4*)&Bs[k][tx * TN + 4];
            #pragma unroll
            for (int i = 0; i < TM; i++)
                #pragma unroll
                for (int j = 0; j < TN; j++)
                    acc[i][j] = fmaf(ra[i], rb[j], acc[i][j]);
        }
        __syncthreads();
    }

    // Epilogue
    #pragma unroll
    for (int i = 0; i < TM; i++) {
        const int row = bm + ty * TM + i;
        float badd = 0.0f;
        float rsv  = 0.0f;
        if (EPI == 0) {
            if (bias) badd = bias[row];
        } else {
            rsv = rs[(size_t)n * BD + row];
        }
        #pragma unroll
        for (int j0 = 0; j0 < TN; j0 += 4) {
            const int col = bn + tx * TN + j0;
            float4 v;
            v.x = acc[i][j0 + 0];
            v.y = acc[i][j0 + 1];
            v.z = acc[i][j0 + 2];
            v.w = acc[i][j0 + 3];
            if (EPI == 0) {
                v.x += badd; v.y += badd; v.z += badd; v.w += badd;
            } else {
                const float* csn = cs + (size_t)n * BD;
                v.x *= rsqrtf(fmaxf(rsv * csn[col + 0], EPSF));
                v.y *= rsqrtf(fmaxf(rsv * csn[col + 1], EPSF));
                v.z *= rsqrtf(fmaxf(rsv * csn[col + 2], EPSF));
                v.w *= rsqrtf(fmaxf(rsv * csn[col + 3], EPSF));
            }
            *(float4*)&C[(size_t)row * N + col] = v;
        }
    }
}

// ---------------------------------------------------------------------------
// Column sum-of-squares over c: DK2[n,b] = sum_c K[n,c,b]^2 (and same for Q).
// One thread per (n,b); loads are coalesced across threads (consecutive b).
// ---------------------------------------------------------------------------
__global__ __launch_bounds__(256)
void colnorm_kernel()
{
    const int idx = blockIdx.x * blockDim.x + threadIdx.x;  // 0 .. NB*BD-1
    const int n = idx / BD;
    const int b = idx % BD;
    const float* Kp = g_K + (size_t)n * CD * BD + b;
    const float* Qp = g_Q + (size_t)n * CD * BD + b;
    float sk = 0.0f, sq = 0.0f;
    #pragma unroll 4
    for (int c = 0; c < CD; c++) {
        float kv = Kp[(size_t)c * BD];
        float qv = Qp[(size_t)c * BD];
        sk = fmaf(kv, kv, sk);
        sq = fmaf(qv, qv, sq);
    }
    g_DK2[idx] = sk;
    g_DQ2[idx] = sq;
}

// ---------------------------------------------------------------------------
// Column softmax over axis q of Y[n, q, k] (in place). One thread per (n,k).
// ---------------------------------------------------------------------------
__global__ __launch_bounds__(256)
void softmax_kernel()
{
    const int idx = blockIdx.x * blockDim.x + threadIdx.x;  // 0 .. NB*BD-1
    const int n = idx / BD;
    const int k = idx % BD;
    float* Yp = g_Y + (size_t)n * BD * BD + k;

    float m = -INFINITY;
    #pragma unroll 4
    for (int q = 0; q < BD; q++)
        m = fmaxf(m, Yp[(size_t)q * BD]);

    float s = 0.0f;
    #pragma unroll 4
    for (int q = 0; q < BD; q++) {
        float e = __expf(Yp[(size_t)q * BD] - m);
        Yp[(size_t)q * BD] = e;
        s += e;
    }

    const float inv = 1.0f / s;
    #pragma unroll 4
    for (int q = 0; q < BD; q++)
        Yp[(size_t)q * BD] *= inv;
}

// ---------------------------------------------------------------------------
// kernel_launch
// inputs: X [N,C,B], Wk [C,C], Wq [C,C], Wk0 [C,1], Wq0 [C,1]; out Z [N,C,B]
// ---------------------------------------------------------------------------
extern "C" void kernel_launch(void* const* d_in, const int* in_sizes, int n_in,
                              void* d_out, int out_size)
{
    const float* X   = (const float*)d_in[0];
    const float* Wk  = (const float*)d_in[1];
    const float* Wq  = (const float*)d_in[2];
    const float* Wk0 = (const float*)d_in[3];
    const float* Wq0 = (const float*)d_in[4];
    float* Z = (float*)d_out;

    float *Kbuf, *Qbuf, *Ybuf, *dk2, *dq2;
    cudaGetSymbolAddress((void**)&Kbuf, g_K);
    cudaGetSymbolAddress((void**)&Qbuf, g_Q);
    cudaGetSymbolAddress((void**)&Ybuf, g_Y);
    cudaGetSymbolAddress((void**)&dk2, g_DK2);
    cudaGetSymbolAddress((void**)&dq2, g_DQ2);

    dim3 grid(BD / BN, CD / BM, NB);
    dim3 gridY(BD / BN, BD / BM, NB);

    // 1) K = Wk @ X[n] + Wk0 ; 2) Q = Wq @ X[n] + Wq0
    gemm_kernel<false, 0><<<grid, 256>>>(Wk, X, Kbuf, CD, BD, CD,
                                         0, (size_t)CD * BD, (size_t)CD * BD,
                                         Wk0, nullptr, nullptr);
    gemm_kernel<false, 0><<<grid, 256>>>(Wq, X, Qbuf, CD, BD, CD,
                                         0, (size_t)CD * BD, (size_t)CD * BD,
                                         Wq0, nullptr, nullptr);

    // 3) DK2 / DQ2 column norms
    colnorm_kernel<<<(NB * BD) / 256, 256>>>();

    // 4) Y[n,q,k] = (Q^T K)[q,k] * rsqrt(max(DQ2[q]*DK2[k], eps))
    gemm_kernel<true, 1><<<gridY, 256>>>(Qbuf, Kbuf, Ybuf, BD, BD, CD,
                                         (size_t)CD * BD, (size_t)CD * BD, (size_t)BD * BD,
                                         nullptr, dq2, dk2);

    // 5) softmax over q, in place -> SM
    softmax_kernel<<<(NB * BD) / 256, 256>>>();

    // 6) Z[n] = X[n] @ SM[n]
    gemm_kernel<false, 0><<<grid, 256>>>(X, Ybuf, Z, CD, BD, BD,
                                         (size_t)CD * BD, (size_t)BD * BD, (size_t)CD * BD,
                                         nullptr, nullptr, nullptr);
}

// round 4
// speedup vs baseline: 3.0919x; 3.0919x over previous
#include <cuda_runtime.h>
#include <cuda_bf16.h>
#include <stdint.h>
#include <math.h>

typedef __nv_bfloat16 bf16;

#define NB   32
#define DIM  1024
#define EPSF 1e-12f

// ---------------- scratch (__device__ globals; no allocations) ----------------
__device__ __align__(128) bf16 g_Wk_hi[DIM*DIM], g_Wk_lo[DIM*DIM];
__device__ __align__(128) bf16 g_Wq_hi[DIM*DIM], g_Wq_lo[DIM*DIM];
__device__ __align__(128) bf16 g_X_hi [NB*DIM*DIM], g_X_lo [NB*DIM*DIM];
__device__ __align__(128) bf16 g_XT_hi[NB*DIM*DIM], g_XT_lo[NB*DIM*DIM];
__device__ __align__(128) bf16 g_KT_hi[NB*DIM*DIM], g_KT_lo[NB*DIM*DIM];
__device__ __align__(128) bf16 g_QT_hi[NB*DIM*DIM], g_QT_lo[NB*DIM*DIM];
__device__ __align__(128) bf16 g_SM_hi[NB*DIM*DIM], g_SM_lo[NB*DIM*DIM];
__device__ __align__(128) float g_YT[NB*DIM*DIM];
__device__ float g_DK2[NB*DIM], g_DQ2[NB*DIM];

// ---------------- helpers ----------------
__device__ __forceinline__ uint32_t smem_to_u32(const void* p) {
    uint32_t a;
    asm("{ .reg .u64 t; cvta.to.shared.u64 t, %1; cvt.u32.u64 %0, t; }" : "=r"(a) : "l"(p));
    return a;
}

#define LDSM4(r, addr) \
    asm volatile("ldmatrix.sync.aligned.m8n8.x4.shared.b16 {%0,%1,%2,%3}, [%4];" \
        : "=r"((r)[0]), "=r"((r)[1]), "=r"((r)[2]), "=r"((r)[3]) : "r"(addr))

#define MMA(acc, a, b0, b1) \
    asm volatile("mma.sync.aligned.m16n8k16.row.col.f32.bf16.bf16.f32 " \
        "{%0,%1,%2,%3}, {%4,%5,%6,%7}, {%8,%9}, {%0,%1,%2,%3};" \
        : "+f"((acc)[0]), "+f"((acc)[1]), "+f"((acc)[2]), "+f"((acc)[3]) \
        : "r"((a)[0]), "r"((a)[1]), "r"((a)[2]), "r"((a)[3]), "r"(b0), "r"(b1))

__device__ __forceinline__ float2 bf2f(uint32_t u) {
    __nv_bfloat162 b = *reinterpret_cast<__nv_bfloat162*>(&u);
    return __bfloat1622float2(b);
}

#define STAGE_BYTES 65536
#define SMEM_BYTES  (2 * STAGE_BYTES)   // 128 KB (epilogue fp32 buffer overlays this)

// ---------------------------------------------------------------------------
// Split-bf16 tensor-core GEMM via mma.sync (baseline ISA, no tcgen05):
// D[m,n] = sum_k A[m,k]*B[n,k]  (both operands K-major)
// CTA 128x128, BK=64 (bf16), 8 warps (2m x 4n), warp tile 64x32.
// 3 passes per k-chunk: Ahi*Bhi + Ahi*Blo + Alo*Bhi (fp32-grade accuracy).
// EPI 0: bf16 hi/lo TRANSPOSED store out[n][m], + bias[m]
// EPI 1: fp32 TRANSPOSED store, * rsqrt(max(rs[m]*cs[n], eps))
// EPI 2: fp32 direct store out[m][n]
// ---------------------------------------------------------------------------
template <int EPI>
__global__ __launch_bounds__(256, 1)
void mma_gemm(const bf16* __restrict__ Ahi, const bf16* __restrict__ Alo, size_t sA,
              const bf16* __restrict__ Bhi, const bf16* __restrict__ Blo, size_t sB,
              float* __restrict__ outF, bf16* __restrict__ oHi, bf16* __restrict__ oLo,
              const float* __restrict__ bias, const float* __restrict__ rs,
              const float* __restrict__ cs)
{
    extern __shared__ char smem[];
    const int tid  = threadIdx.x;
    const int lane = tid & 31, warp = tid >> 5;
    const int wm = (warp >> 2) * 64, wn = (warp & 3) * 32;
    const int bz = blockIdx.z;
    const int bm = blockIdx.y * 128, bn = blockIdx.x * 128;
    const uint32_t sbase = smem_to_u32(smem);

    const bf16* pAh = Ahi + (size_t)bz * sA + (size_t)bm * DIM;
    const bf16* pAl = Alo + (size_t)bz * sA + (size_t)bm * DIM;
    const bf16* pBh = Bhi + (size_t)bz * sB + (size_t)bn * DIM;
    const bf16* pBl = Blo + (size_t)bz * sB + (size_t)bn * DIM;

    // tile: 128 rows x 64 bf16 (128B rows), 16B chunk c swizzled: p = c ^ (row&7)
    auto load_tile = [&](uint32_t dst, const bf16* src) {
        #pragma unroll
        for (int i = 0; i < 4; i++) {
            int cid = tid + i * 256;          // 0..1023 chunks
            int r = cid >> 3, c = cid & 7;
            uint32_t p = (uint32_t)(c ^ (r & 7));
            asm volatile("cp.async.cg.shared.global [%0], [%1], 16;"
                         :: "r"(dst + (uint32_t)(r * 128 + p * 16)),
                            "l"(src + (size_t)r * DIM + c * 8));
        }
    };
    auto load_stage = [&](int s, int kc) {
        uint32_t st = sbase + (uint32_t)s * STAGE_BYTES;
        load_tile(st,         pAh + kc);
        load_tile(st + 16384, pAl + kc);
        load_tile(st + 32768, pBh + kc);
        load_tile(st + 49152, pBl + kc);
        asm volatile("cp.async.commit_group;" ::: "memory");
    };

    float acc[4][4][4];
    #pragma unroll
    for (int a = 0; a < 4; a++)
        #pragma unroll
        for (int b = 0; b < 4; b++)
            #pragma unroll
            for (int c = 0; c < 4; c++)
                acc[a][b][c] = 0.0f;

    load_stage(0, 0);

    for (int i = 0; i < 16; i++) {
        if (i + 1 < 16) {
            load_stage((i + 1) & 1, (i + 1) * 64);
            asm volatile("cp.async.wait_group 1;" ::: "memory");
        } else {
            asm volatile("cp.async.wait_group 0;" ::: "memory");
        }
        __syncthreads();

        const uint32_t Ahb = sbase + (uint32_t)(i & 1) * STAGE_BYTES;
        const uint32_t Alb = Ahb + 16384, Bhb = Ahb + 32768, Blb = Ahb + 49152;

        #pragma unroll
        for (int kk = 0; kk < 4; kk++) {
            uint32_t ah[4][4], al[4][4], bh[8], bl[8];
            // A fragments: row = wm + im*16 + (lane&15), k-half = lane>>4
            const int arow = wm + (lane & 15);
            const uint32_t ac = (uint32_t)(kk * 2 + (lane >> 4));
            #pragma unroll
            for (int im = 0; im < 4; im++) {
                int r = arow + im * 16;
                uint32_t p = ac ^ (uint32_t)(r & 7);
                LDSM4(ah[im], Ahb + (uint32_t)(r * 128) + p * 16);
                LDSM4(al[im], Alb + (uint32_t)(r * 128) + p * 16);
            }
            // B fragments: rows n, x4 covers n16 x k16
            const int brow = wn + ((lane >> 4) << 3) + (lane & 7);
            const uint32_t bc = (uint32_t)(kk * 2 + ((lane >> 3) & 1));
            #pragma unroll
            for (int g = 0; g < 2; g++) {
                int r = brow + g * 16;
                uint32_t p = bc ^ (uint32_t)(r & 7);
                LDSM4(&bh[g * 4], Bhb + (uint32_t)(r * 128) + p * 16);
                LDSM4(&bl[g * 4], Blb + (uint32_t)(r * 128) + p * 16);
            }
            #pragma unroll
            for (int im = 0; im < 4; im++)
                #pragma unroll
                for (int jn = 0; jn < 4; jn++) {
                    MMA(acc[im][jn], ah[im], bh[2 * jn], bh[2 * jn + 1]);
                    MMA(acc[im][jn], ah[im], bl[2 * jn], bl[2 * jn + 1]);
                    MMA(acc[im][jn], al[im], bh[2 * jn], bh[2 * jn + 1]);
                }
        }
        __syncthreads();
    }

    // ---- epilogue: stage through padded fp32 smem for coalesced stores ----
    float* sfl = (float*)smem;   // [128][129]
    #pragma unroll
    for (int im = 0; im < 4; im++)
        #pragma unroll
        for (int jn = 0; jn < 4; jn++) {
            int m  = wm + im * 16 + (lane >> 2);
            int nn = wn + jn * 8 + 2 * (lane & 3);
            sfl[m * 129 + nn]           = acc[im][jn][0];
            sfl[m * 129 + nn + 1]       = acc[im][jn][1];
            sfl[(m + 8) * 129 + nn]     = acc[im][jn][2];
            sfl[(m + 8) * 129 + nn + 1] = acc[im][jn][3];
        }
    __syncthreads();

    const size_t obase = (size_t)bz * (size_t)(DIM * DIM);
    #pragma unroll 1
    for (int idx = tid; idx < 128 * 128; idx += 256) {
        if (EPI == 2) {
            int m = idx >> 7, nn = idx & 127;
            outF[obase + (size_t)(bm + m) * DIM + bn + nn] = sfl[m * 129 + nn];
        } else {
            int nn = idx >> 7, m = idx & 127;
            float v = sfl[m * 129 + nn];
            if (EPI == 0) {
                v += bias[bm + m];
                bf16 h = __float2bfloat16(v);
                bf16 l = __float2bfloat16(v - __bfloat162float(h));
                size_t o = obase + (size_t)(bn + nn) * DIM + bm + m;
                oHi[o] = h; oLo[o] = l;
            } else {
                float sc = rsqrtf(fmaxf(rs[bz * DIM + bm + m] * cs[bz * DIM + bn + nn], EPSF));
                outF[obase + (size_t)(bn + nn) * DIM + bm + m] = v * sc;
            }
        }
    }
}

// ---------------------------------------------------------------------------
// Elementwise kernels
// ---------------------------------------------------------------------------
__global__ __launch_bounds__(256)
void w_split(const float* __restrict__ Wk, const float* __restrict__ Wq)
{
    int i = blockIdx.x * 256 + threadIdx.x;
    float a = Wk[i];
    bf16 h = __float2bfloat16(a);
    g_Wk_hi[i] = h; g_Wk_lo[i] = __float2bfloat16(a - __bfloat162float(h));
    float b = Wq[i];
    h = __float2bfloat16(b);
    g_Wq_hi[i] = h; g_Wq_lo[i] = __float2bfloat16(b - __bfloat162float(h));
}

// X[n][d][b] -> X_hi/lo (same layout) + XT_hi/lo [n][b][d]
__global__ __launch_bounds__(256)
void xprep(const float* __restrict__ X)
{
    __shared__ float t[32][33];
    const int n = blockIdx.z, b0 = blockIdx.x * 32, d0 = blockIdx.y * 32;
    const int tx = threadIdx.x, ty = threadIdx.y;
    const size_t base = (size_t)n << 20;
    const float* Xn = X + base;
    #pragma unroll
    for (int r = 0; r < 4; r++) {
        int row = ty + r * 8;
        float v = Xn[(size_t)(d0 + row) * DIM + b0 + tx];
        t[row][tx] = v;
        bf16 h = __float2bfloat16(v);
        size_t o = base + (size_t)(d0 + row) * DIM + b0 + tx;
        g_X_hi[o] = h; g_X_lo[o] = __float2bfloat16(v - __bfloat162float(h));
    }
    __syncthreads();
    #pragma unroll
    for (int r = 0; r < 4; r++) {
        int row = ty + r * 8;
        float v = t[tx][row];                    // = X[d0+tx][b0+row]
        bf16 h = __float2bfloat16(v);
        size_t o = base + (size_t)(b0 + row) * DIM + d0 + tx;
        g_XT_hi[o] = h; g_XT_lo[o] = __float2bfloat16(v - __bfloat162float(h));
    }
}

// DK2[n,b] = sum_c K[n,c,b]^2 from KT rows (hi+lo); same for Q. one warp/row.
__global__ __launch_bounds__(256)
void norms_k()
{
    const int gw  = (blockIdx.x * 256 + threadIdx.x) >> 5;
    const int lid = threadIdx.x & 31;
    const size_t rb = (size_t)gw << 10;
    const bf16 *kh = g_KT_hi + rb, *kl = g_KT_lo + rb;
    const bf16 *qh = g_QT_hi + rb, *ql = g_QT_lo + rb;
    float sk = 0.f, sq = 0.f;
    #pragma unroll
    for (int c = 0; c < 4; c++) {
        int off = c * 256 + lid * 8;
        uint4 vh = *(const uint4*)(kh + off);
        uint4 vl = *(const uint4*)(kl + off);
        uint4 wh = *(const uint4*)(qh + off);
        uint4 wl = *(const uint4*)(ql + off);
        const uint32_t* ph = (const uint32_t*)&vh;
        const uint32_t* pl = (const uint32_t*)&vl;
        const uint32_t* rh = (const uint32_t*)&wh;
        const uint32_t* rl = (const uint32_t*)&wl;
        #pragma unroll
        for (int u = 0; u < 4; u++) {
            float2 a = bf2f(ph[u]), b = bf2f(pl[u]);
            float x0 = a.x + b.x, x1 = a.y + b.y;
            sk = fmaf(x0, x0, sk); sk = fmaf(x1, x1, sk);
            float2 cq = bf2f(rh[u]), dq = bf2f(rl[u]);
            x0 = cq.x + dq.x; x1 = cq.y + dq.y;
            sq = fmaf(x0, x0, sq); sq = fmaf(x1, x1, sq);
        }
    }
    #pragma unroll
    for (int o = 16; o > 0; o >>= 1) {
        sk += __shfl_xor_sync(0xFFFFFFFFu, sk, o);
        sq += __shfl_xor_sync(0xFFFFFFFFu, sq, o);
    }
    if (lid == 0) { g_DK2[gw] = sk; g_DQ2[gw] = sq; }
}

// Row softmax of YT (each row = one softmax column of Y), write SM hi/lo bf16.
__global__ __launch_bounds__(256)
void softmax_k()
{
    const int row = blockIdx.x;
    const int tid = threadIdx.x;
    float* y = g_YT + ((size_t)row << 10);
    float v[4];
    #pragma unroll
    for (int j = 0; j < 4; j++) v[j] = y[tid + j * 256];
    float m = fmaxf(fmaxf(v[0], v[1]), fmaxf(v[2], v[3]));
    __shared__ float red[8];
    #pragma unroll
    for (int o = 16; o > 0; o >>= 1) m = fmaxf(m, __shfl_xor_sync(0xFFFFFFFFu, m, o));
    if ((tid & 31) == 0) red[tid >> 5] = m;
    __syncthreads();
    float mall = red[0];
    #pragma unroll
    for (int w = 1; w < 8; w++) mall = fmaxf(mall, red[w]);
    float s = 0.f;
    #pragma unroll
    for (int j = 0; j < 4; j++) { v[j] = __expf(v[j] - mall); s += v[j]; }
    #pragma unroll
    for (int o = 16; o > 0; o >>= 1) s += __shfl_xor_sync(0xFFFFFFFFu, s, o);
    __syncthreads();
    if ((tid & 31) == 0) red[tid >> 5] = s;
    __syncthreads();
    float st = 0.f;
    #pragma unroll
    for (int w = 0; w < 8; w++) st += red[w];
    const float inv = 1.0f / st;
    #pragma unroll
    for (int j = 0; j < 4; j++) {
        float p = v[j] * inv;
        bf16 h = __float2bfloat16(p);
        size_t o = ((size_t)row << 10) + tid + j * 256;
        g_SM_hi[o] = h;
        g_SM_lo[o] = __float2bfloat16(p - __bfloat162float(h));
    }
}

// ---------------------------------------------------------------------------
extern "C" void kernel_launch(void* const* d_in, const int* in_sizes, int n_in,
                              void* d_out, int out_size)
{
    const float* X   = (const float*)d_in[0];
    const float* Wk  = (const float*)d_in[1];
    const float* Wq  = (const float*)d_in[2];
    const float* Wk0 = (const float*)d_in[3];
    const float* Wq0 = (const float*)d_in[4];
    float* Z = (float*)d_out;

    cudaFuncSetAttribute(mma_gemm<0>, cudaFuncAttributeMaxDynamicSharedMemorySize, SMEM_BYTES);
    cudaFuncSetAttribute(mma_gemm<1>, cudaFuncAttributeMaxDynamicSharedMemorySize, SMEM_BYTES);
    cudaFuncSetAttribute(mma_gemm<2>, cudaFuncAttributeMaxDynamicSharedMemorySize, SMEM_BYTES);

    bf16 *Wkh, *Wkl, *Wqh, *Wql, *Xh, *Xl, *XTh, *XTl, *KTh, *KTl, *QTh, *QTl, *SMh, *SMl;
    float *YT, *dk2, *dq2;
    cudaGetSymbolAddress((void**)&Wkh, g_Wk_hi);  cudaGetSymbolAddress((void**)&Wkl, g_Wk_lo);
    cudaGetSymbolAddress((void**)&Wqh, g_Wq_hi);  cudaGetSymbolAddress((void**)&Wql, g_Wq_lo);
    cudaGetSymbolAddress((void**)&Xh,  g_X_hi);   cudaGetSymbolAddress((void**)&Xl,  g_X_lo);
    cudaGetSymbolAddress((void**)&XTh, g_XT_hi);  cudaGetSymbolAddress((void**)&XTl, g_XT_lo);
    cudaGetSymbolAddress((void**)&KTh, g_KT_hi);  cudaGetSymbolAddress((void**)&KTl, g_KT_lo);
    cudaGetSymbolAddress((void**)&QTh, g_QT_hi);  cudaGetSymbolAddress((void**)&QTl, g_QT_lo);
    cudaGetSymbolAddress((void**)&SMh, g_SM_hi);  cudaGetSymbolAddress((void**)&SMl, g_SM_lo);
    cudaGetSymbolAddress((void**)&YT,  g_YT);
    cudaGetSymbolAddress((void**)&dk2, g_DK2);    cudaGetSymbolAddress((void**)&dq2, g_DQ2);

    const size_t S = (size_t)DIM * DIM;
    dim3 gg(8, 8, NB);

    w_split<<<(DIM * DIM) / 256, 256>>>(Wk, Wq);
    xprep<<<dim3(32, 32, NB), dim3(32, 8)>>>(X);

    // KT[b,c] = (Wk @ X)^T + Wk0 ; QT likewise (bf16 split, transposed store)
    mma_gemm<0><<<gg, 256, SMEM_BYTES>>>(Wkh, Wkl, 0, XTh, XTl, S,
                                         nullptr, KTh, KTl, Wk0, nullptr, nullptr);
    mma_gemm<0><<<gg, 256, SMEM_BYTES>>>(Wqh, Wql, 0, XTh, XTl, S,
                                         nullptr, QTh, QTl, Wq0, nullptr, nullptr);
    norms_k<<<(NB * DIM) / 8, 256>>>();

    // YT[k,q] = (Q^T K)[q,k] * rsqrt(max(DQ2[q]*DK2[k], eps))
    mma_gemm<1><<<gg, 256, SMEM_BYTES>>>(QTh, QTl, S, KTh, KTl, S,
                                         YT, nullptr, nullptr, nullptr, dq2, dk2);
    softmax_k<<<NB * DIM, 256>>>();

    // Z[c,q] = X @ SM (SM rows are already the K-major B operand)
    mma_gemm<2><<<gg, 256, SMEM_BYTES>>>(Xh, Xl, S, SMh, SMl, S,
                                         Z, nullptr, nullptr, nullptr, nullptr, nullptr);
}

// round 6
// speedup vs baseline: 3.2238x; 1.0427x over previous
#include <cuda_runtime.h>
#include <cuda_bf16.h>
#include <stdint.h>
#include <math.h>

typedef __nv_bfloat16 bf16;

#define NB   32
#define DIM  1024
#define EPSF 1e-12f

// ---------------- scratch (__device__ globals; no allocations) ----------------
__device__ __align__(128) bf16 g_Wk_hi[DIM*DIM], g_Wk_lo[DIM*DIM];
__device__ __align__(128) bf16 g_Wq_hi[DIM*DIM], g_Wq_lo[DIM*DIM];
__device__ __align__(128) bf16 g_X_hi [NB*DIM*DIM], g_X_lo [NB*DIM*DIM];
__device__ __align__(128) bf16 g_XT_hi[NB*DIM*DIM], g_XT_lo[NB*DIM*DIM];
__device__ __align__(128) bf16 g_KT_hi[NB*DIM*DIM], g_KT_lo[NB*DIM*DIM];
__device__ __align__(128) bf16 g_QT_hi[NB*DIM*DIM], g_QT_lo[NB*DIM*DIM];
__device__ __align__(128) bf16 g_SM_hi[NB*DIM*DIM], g_SM_lo[NB*DIM*DIM];
__device__ __align__(128) float g_YT[NB*DIM*DIM];
__device__ float g_DK2[NB*DIM], g_DQ2[NB*DIM];

// ---------------- helpers ----------------
__device__ __forceinline__ uint32_t smem_to_u32(const void* p) {
    uint32_t a;
    asm("{ .reg .u64 t; cvta.to.shared.u64 t, %1; cvt.u32.u64 %0, t; }" : "=r"(a) : "l"(p));
    return a;
}

#define LDSM4(r, addr) \
    asm volatile("ldmatrix.sync.aligned.m8n8.x4.shared.b16 {%0,%1,%2,%3}, [%4];" \
        : "=r"((r)[0]), "=r"((r)[1]), "=r"((r)[2]), "=r"((r)[3]) : "r"(addr))

#define MMA(acc, a, b0, b1) \
    asm volatile("mma.sync.aligned.m16n8k16.row.col.f32.bf16.bf16.f32 " \
        "{%0,%1,%2,%3}, {%4,%5,%6,%7}, {%8,%9}, {%0,%1,%2,%3};" \
        : "+f"((acc)[0]), "+f"((acc)[1]), "+f"((acc)[2]), "+f"((acc)[3]) \
        : "r"((a)[0]), "r"((a)[1]), "r"((a)[2]), "r"((a)[3]), "r"(b0), "r"(b1))

__device__ __forceinline__ float2 bf2f(uint32_t u) {
    __nv_bfloat162 b = *reinterpret_cast<__nv_bfloat162*>(&u);
    return __bfloat1622float2(b);
}

// Stage: A-combined tile (128 rows x [hi 64B | lo 64B]) 16KB + B-combined 16KB
#define STAGE_BYTES 32768
#define NSTAGE 3
#define SMEM_BYTES (NSTAGE * STAGE_BYTES)   // 96 KB; epilogue fp32 [128][129] = 66 KB overlays

// ---------------------------------------------------------------------------
// Split-bf16 tensor-core GEMM via mma.sync:
// D[m,n] = sum_k A[m,k]*B[n,k]  (both operands K-major)
// CTA 128x128, BK=32, 3-stage cp.async pipeline, 2 CTAs/SM.
// hi/lo packed per 128B smem row; conflict-free SW128 swizzle p = c ^ (r&7).
// 3 passes: Ahi*Bhi + Ahi*Blo + Alo*Bhi.
// EPI 0: bf16 hi/lo TRANSPOSED store out[n][m], + bias[m]
// EPI 1: fp32 TRANSPOSED store, * rsqrt(max(rs[m]*cs[n], eps))
// EPI 2: fp32 direct store out[m][n]
// ---------------------------------------------------------------------------
template <int EPI>
__global__ __launch_bounds__(256, 2)
void mma_gemm(const bf16* __restrict__ Ahi, const bf16* __restrict__ Alo, size_t sA,
              const bf16* __restrict__ Bhi, const bf16* __restrict__ Blo, size_t sB,
              float* __restrict__ outF, bf16* __restrict__ oHi, bf16* __restrict__ oLo,
              const float* __restrict__ bias, const float* __restrict__ rs,
              const float* __restrict__ cs)
{
    extern __shared__ char smem[];
    const int tid  = threadIdx.x;
    const int lane = tid & 31, warp = tid >> 5;
    const int wm = (warp >> 2) * 64, wn = (warp & 3) * 32;
    const int bz = blockIdx.z;
    const int bm = blockIdx.y * 128, bn = blockIdx.x * 128;
    const uint32_t sbase = smem_to_u32(smem);

    const bf16* pAh = Ahi + (size_t)bz * sA + (size_t)bm * DIM;
    const bf16* pAl = Alo + (size_t)bz * sA + (size_t)bm * DIM;
    const bf16* pBh = Bhi + (size_t)bz * sB + (size_t)bn * DIM;
    const bf16* pBl = Blo + (size_t)bz * sB + (size_t)bn * DIM;

    // combined tile: 128 rows x 128B; chunks c<4 = hi k[0..31], c>=4 = lo k[0..31]
    auto load_combined = [&](uint32_t dst, const bf16* hi, const bf16* lo, int kc) {
        #pragma unroll
        for (int i = 0; i < 4; i++) {
            int cid = tid + i * 256;          // 0..1023
            int r = cid >> 3, c = cid & 7;
            const bf16* src = (c < 4) ? (hi + (size_t)r * DIM + kc + c * 8)
                                      : (lo + (size_t)r * DIM + kc + (c - 4) * 8);
            uint32_t p = (uint32_t)(c ^ (r & 7));
            asm volatile("cp.async.cg.shared.global [%0], [%1], 16;"
                         :: "r"(dst + (uint32_t)(r * 128 + p * 16)), "l"(src));
        }
    };
    auto load_stage = [&](int s, int kc) {
        uint32_t st = sbase + (uint32_t)s * STAGE_BYTES;
        load_combined(st,         pAh, pAl, kc);
        load_combined(st + 16384, pBh, pBl, kc);
        asm volatile("cp.async.commit_group;" ::: "memory");
    };

    float acc[4][4][4];
    #pragma unroll
    for (int a = 0; a < 4; a++)
        #pragma unroll
        for (int b = 0; b < 4; b++)
            #pragma unroll
            for (int c = 0; c < 4; c++)
                acc[a][b][c] = 0.0f;

    load_stage(0, 0);
    load_stage(1, 32);

    const int NCHUNK = 32;   // K / 32
    for (int i = 0; i < NCHUNK; i++) {
        if (i + 2 < NCHUNK) {
            load_stage((i + 2) % NSTAGE, (i + 2) * 32);
            asm volatile("cp.async.wait_group 2;" ::: "memory");
        } else if (i + 1 < NCHUNK) {
            asm volatile("cp.async.wait_group 1;" ::: "memory");
        } else {
            asm volatile("cp.async.wait_group 0;" ::: "memory");
        }
        __syncthreads();

        const uint32_t Ab = sbase + (uint32_t)(i % NSTAGE) * STAGE_BYTES;
        const uint32_t Bb = Ab + 16384;

        #pragma unroll
        for (int kk = 0; kk < 2; kk++) {
            uint32_t bh[8], bl[8];
            const int brow = wn + ((lane >> 4) << 3) + (lane & 7);
            const uint32_t bc = (uint32_t)(kk * 2 + ((lane >> 3) & 1));
            #pragma unroll
            for (int g = 0; g < 2; g++) {
                int r = brow + g * 16;
                uint32_t ph = (bc ^ (uint32_t)(r & 7));
                uint32_t pl = ((bc + 4) ^ (uint32_t)(r & 7));
                LDSM4(&bh[g * 4], Bb + (uint32_t)(r * 128) + ph * 16);
                LDSM4(&bl[g * 4], Bb + (uint32_t)(r * 128) + pl * 16);
            }
            const int arow = wm + (lane & 15);
            const uint32_t ac = (uint32_t)(kk * 2 + (lane >> 4));
            #pragma unroll
            for (int im = 0; im < 4; im++) {
                uint32_t ah[4], al[4];
                int r = arow + im * 16;
                uint32_t ph = (ac ^ (uint32_t)(r & 7));
                uint32_t pl = ((ac + 4) ^ (uint32_t)(r & 7));
                LDSM4(ah, Ab + (uint32_t)(r * 128) + ph * 16);
                LDSM4(al, Ab + (uint32_t)(r * 128) + pl * 16);
                #pragma unroll
                for (int jn = 0; jn < 4; jn++) {
                    MMA(acc[im][jn], ah, bh[2 * jn], bh[2 * jn + 1]);
                    MMA(acc[im][jn], ah, bl[2 * jn], bl[2 * jn + 1]);
                    MMA(acc[im][jn], al, bh[2 * jn], bh[2 * jn + 1]);
                }
            }
        }
        __syncthreads();
    }

    // ---- epilogue: stage through padded fp32 smem for coalesced stores ----
    float* sfl = (float*)smem;   // [128][129] = 66048 B < SMEM_BYTES
    #pragma unroll
    for (int im = 0; im < 4; im++)
        #pragma unroll
        for (int jn = 0; jn < 4; jn++) {
            int m  = wm + im * 16 + (lane >> 2);
            int nn = wn + jn * 8 + 2 * (lane & 3);
            sfl[m * 129 + nn]           = acc[im][jn][0];
            sfl[m * 129 + nn + 1]       = acc[im][jn][1];
            sfl[(m + 8) * 129 + nn]     = acc[im][jn][2];
            sfl[(m + 8) * 129 + nn + 1] = acc[im][jn][3];
        }
    __syncthreads();

    const size_t obase = (size_t)bz * (size_t)(DIM * DIM);
    #pragma unroll 1
    for (int idx = tid; idx < 128 * 128; idx += 256) {
        if (EPI == 2) {
            int m = idx >> 7, nn = idx & 127;
            outF[obase + (size_t)(bm + m) * DIM + bn + nn] = sfl[m * 129 + nn];
        } else {
            int nn = idx >> 7, m = idx & 127;
            float v = sfl[m * 129 + nn];
            if (EPI == 0) {
                v += bias[bm + m];
                bf16 h = __float2bfloat16(v);
                bf16 l = __float2bfloat16(v - __bfloat162float(h));
                size_t o = obase + (size_t)(bn + nn) * DIM + bm + m;
                oHi[o] = h; oLo[o] = l;
            } else {
                float sc = rsqrtf(fmaxf(rs[bz * DIM + bm + m] * cs[bz * DIM + bn + nn], EPSF));
                outF[obase + (size_t)(bn + nn) * DIM + bm + m] = v * sc;
            }
        }
    }
}

// ---------------------------------------------------------------------------
// Elementwise kernels
// ---------------------------------------------------------------------------
__global__ __launch_bounds__(256)
void w_split(const float* __restrict__ Wk, const float* __restrict__ Wq)
{
    int i = blockIdx.x * 256 + threadIdx.x;
    float a = Wk[i];
    bf16 h = __float2bfloat16(a);
    g_Wk_hi[i] = h; g_Wk_lo[i] = __float2bfloat16(a - __bfloat162float(h));
    float b = Wq[i];
    h = __float2bfloat16(b);
    g_Wq_hi[i] = h; g_Wq_lo[i] = __float2bfloat16(b - __bfloat162float(h));
}

// X[n][d][b] -> X_hi/lo (same layout) + XT_hi/lo [n][b][d]
__global__ __launch_bounds__(256)
void xprep(const float* __restrict__ X)
{
    __shared__ float t[32][33];
    const int n = blockIdx.z, b0 = blockIdx.x * 32, d0 = blockIdx.y * 32;
    const int tx = threadIdx.x, ty = threadIdx.y;
    const size_t base = (size_t)n << 20;
    const float* Xn = X + base;
    #pragma unroll
    for (int r = 0; r < 4; r++) {
        int row = ty + r * 8;
        float v = Xn[(size_t)(d0 + row) * DIM + b0 + tx];
        t[row][tx] = v;
        bf16 h = __float2bfloat16(v);
        size_t o = base + (size_t)(d0 + row) * DIM + b0 + tx;
        g_X_hi[o] = h; g_X_lo[o] = __float2bfloat16(v - __bfloat162float(h));
    }
    __syncthreads();
    #pragma unroll
    for (int r = 0; r < 4; r++) {
        int row = ty + r * 8;
        float v = t[tx][row];                    // = X[d0+tx][b0+row]
        bf16 h = __float2bfloat16(v);
        size_t o = base + (size_t)(b0 + row) * DIM + d0 + tx;
        g_XT_hi[o] = h; g_XT_lo[o] = __float2bfloat16(v - __bfloat162float(h));
    }
}

// DK2[n,b] = sum_c K[n,c,b]^2 from KT rows (hi+lo); same for Q. one warp/row.
__global__ __launch_bounds__(256)
void norms_k()
{
    const int gw  = (blockIdx.x * 256 + threadIdx.x) >> 5;
    const int lid = threadIdx.x & 31;
    const size_t rb = (size_t)gw << 10;
    const bf16 *kh = g_KT_hi + rb, *kl = g_KT_lo + rb;
    const bf16 *qh = g_QT_hi + rb, *ql = g_QT_lo + rb;
    float sk = 0.f, sq = 0.f;
    #pragma unroll
    for (int c = 0; c < 4; c++) {
        int off = c * 256 + lid * 8;
        uint4 vh = *(const uint4*)(kh + off);
        uint4 vl = *(const uint4*)(kl + off);
        uint4 wh = *(const uint4*)(qh + off);
        uint4 wl = *(const uint4*)(ql + off);
        const uint32_t* ph = (const uint32_t*)&vh;
        const uint32_t* pl = (const uint32_t*)&vl;
        const uint32_t* rh = (const uint32_t*)&wh;
        const uint32_t* rl = (const uint32_t*)&wl;
        #pragma unroll
        for (int u = 0; u < 4; u++) {
            float2 a = bf2f(ph[u]), b = bf2f(pl[u]);
            float x0 = a.x + b.x, x1 = a.y + b.y;
            sk = fmaf(x0, x0, sk); sk = fmaf(x1, x1, sk);
            float2 cq = bf2f(rh[u]), dq = bf2f(rl[u]);
            x0 = cq.x + dq.x; x1 = cq.y + dq.y;
            sq = fmaf(x0, x0, sq); sq = fmaf(x1, x1, sq);
        }
    }
    #pragma unroll
    for (int o = 16; o > 0; o >>= 1) {
        sk += __shfl_xor_sync(0xFFFFFFFFu, sk, o);
        sq += __shfl_xor_sync(0xFFFFFFFFu, sq, o);
    }
    if (lid == 0) { g_DK2[gw] = sk; g_DQ2[gw] = sq; }
}

// Row softmax of YT (each row = one softmax column of Y), write SM hi/lo bf16.
__global__ __launch_bounds__(256)
void softmax_k()
{
    const int row = blockIdx.x;
    const int tid = threadIdx.x;
    float* y = g_YT + ((size_t)row << 10);
    float v[4];
    #pragma unroll
    for (int j = 0; j < 4; j++) v[j] = y[tid + j * 256];
    float m = fmaxf(fmaxf(v[0], v[1]), fmaxf(v[2], v[3]));
    __shared__ float red[8];
    #pragma unroll
    for (int o = 16; o > 0; o >>= 1) m = fmaxf(m, __shfl_xor_sync(0xFFFFFFFFu, m, o));
    if ((tid & 31) == 0) red[tid >> 5] = m;
    __syncthreads();
    float mall = red[0];
    #pragma unroll
    for (int w = 1; w < 8; w++) mall = fmaxf(mall, red[w]);
    float s = 0.f;
    #pragma unroll
    for (int j = 0; j < 4; j++) { v[j] = __expf(v[j] - mall); s += v[j]; }
    #pragma unroll
    for (int o = 16; o > 0; o >>= 1) s += __shfl_xor_sync(0xFFFFFFFFu, s, o);
    __syncthreads();
    if ((tid & 31) == 0) red[tid >> 5] = s;
    __syncthreads();
    float st = 0.f;
    #pragma unroll
    for (int w = 0; w < 8; w++) st += red[w];
    const float inv = 1.0f / st;
    #pragma unroll
    for (int j = 0; j < 4; j++) {
        float p = v[j] * inv;
        bf16 h = __float2bfloat16(p);
        size_t o = ((size_t)row << 10) + tid + j * 256;
        g_SM_hi[o] = h;
        g_SM_lo[o] = __float2bfloat16(p - __bfloat162float(h));
    }
}

// ---------------------------------------------------------------------------
extern "C" void kernel_launch(void* const* d_in, const int* in_sizes, int n_in,
                              void* d_out, int out_size)
{
    const float* X   = (const float*)d_in[0];
    const float* Wk  = (const float*)d_in[1];
    const float* Wq  = (const float*)d_in[2];
    const float* Wk0 = (const float*)d_in[3];
    const float* Wq0 = (const float*)d_in[4];
    float* Z = (float*)d_out;

    cudaFuncSetAttribute(mma_gemm<0>, cudaFuncAttributeMaxDynamicSharedMemorySize, SMEM_BYTES);
    cudaFuncSetAttribute(mma_gemm<1>, cudaFuncAttributeMaxDynamicSharedMemorySize, SMEM_BYTES);
    cudaFuncSetAttribute(mma_gemm<2>, cudaFuncAttributeMaxDynamicSharedMemorySize, SMEM_BYTES);

    bf16 *Wkh, *Wkl, *Wqh, *Wql, *Xh, *Xl, *XTh, *XTl, *KTh, *KTl, *QTh, *QTl, *SMh, *SMl;
    float *YT, *dk2, *dq2;
    cudaGetSymbolAddress((void**)&Wkh, g_Wk_hi);  cudaGetSymbolAddress((void**)&Wkl, g_Wk_lo);
    cudaGetSymbolAddress((void**)&Wqh, g_Wq_hi);  cudaGetSymbolAddress((void**)&Wql, g_Wq_lo);
    cudaGetSymbolAddress((void**)&Xh,  g_X_hi);   cudaGetSymbolAddress((void**)&Xl,  g_X_lo);
    cudaGetSymbolAddress((void**)&XTh, g_XT_hi);  cudaGetSymbolAddress((void**)&XTl, g_XT_lo);
    cudaGetSymbolAddress((void**)&KTh, g_KT_hi);  cudaGetSymbolAddress((void**)&KTl, g_KT_lo);
    cudaGetSymbolAddress((void**)&QTh, g_QT_hi);  cudaGetSymbolAddress((void**)&QTl, g_QT_lo);
    cudaGetSymbolAddress((void**)&SMh, g_SM_hi);  cudaGetSymbolAddress((void**)&SMl, g_SM_lo);
    cudaGetSymbolAddress((void**)&YT,  g_YT);
    cudaGetSymbolAddress((void**)&dk2, g_DK2);    cudaGetSymbolAddress((void**)&dq2, g_DQ2);

    const size_t S = (size_t)DIM * DIM;
    dim3 gg(8, 8, NB);

    w_split<<<(DIM * DIM) / 256, 256>>>(Wk, Wq);
    xprep<<<dim3(32, 32, NB), dim3(32, 8)>>>(X);

    // KT[b,c] = (Wk @ X)^T + Wk0 ; QT likewise (bf16 split, transposed store)
    mma_gemm<0><<<gg, 256, SMEM_BYTES>>>(Wkh, Wkl, 0, XTh, XTl, S,
                                         nullptr, KTh, KTl, Wk0, nullptr, nullptr);
    mma_gemm<0><<<gg, 256, SMEM_BYTES>>>(Wqh, Wql, 0, XTh, XTl, S,
                                         nullptr, QTh, QTl, Wq0, nullptr, nullptr);
    norms_k<<<(NB * DIM) / 8, 256>>>();

    // YT[k,q] = (Q^T K)[q,k] * rsqrt(max(DQ2[q]*DK2[k], eps))
    mma_gemm<1><<<gg, 256, SMEM_BYTES>>>(QTh, QTl, S, KTh, KTl, S,
                                         YT, nullptr, nullptr, nullptr, dq2, dk2);
    softmax_k<<<NB * DIM, 256>>>();

    // Z[c,q] = X @ SM (SM rows are already the K-major B operand)
    mma_gemm<2><<<gg, 256, SMEM_BYTES>>>(Xh, Xl, S, SMh, SMl, S,
                                         Z, nullptr, nullptr, nullptr, nullptr, nullptr);
}

// round 7
// speedup vs baseline: 3.3171x; 1.0289x over previous
#include <cuda_runtime.h>
#include <cuda_bf16.h>
#include <stdint.h>
#include <math.h>

typedef __nv_bfloat16 bf16;

#define NB   32
#define DIM  1024
#define EPSF 1e-12f

// ---------------- scratch (__device__ globals; no allocations) ----------------
__device__ __align__(128) bf16 g_Wk_hi[DIM*DIM], g_Wk_lo[DIM*DIM];
__device__ __align__(128) bf16 g_Wq_hi[DIM*DIM], g_Wq_lo[DIM*DIM];
__device__ __align__(128) bf16 g_X_hi [NB*DIM*DIM], g_X_lo [NB*DIM*DIM];
__device__ __align__(128) bf16 g_XT_hi[NB*DIM*DIM], g_XT_lo[NB*DIM*DIM];
__device__ __align__(128) bf16 g_KT_hi[NB*DIM*DIM], g_KT_lo[NB*DIM*DIM];
__device__ __align__(128) bf16 g_QT_hi[NB*DIM*DIM], g_QT_lo[NB*DIM*DIM];
__device__ __align__(128) bf16 g_SM_hi[NB*DIM*DIM], g_SM_lo[NB*DIM*DIM];
__device__ __align__(128) float g_YT[NB*DIM*DIM];
__device__ float g_DK2[NB*DIM], g_DQ2[NB*DIM];

// ---------------- helpers ----------------
__device__ __forceinline__ uint32_t smem_to_u32(const void* p) {
    uint32_t a;
    asm("{ .reg .u64 t; cvta.to.shared.u64 t, %1; cvt.u32.u64 %0, t; }" : "=r"(a) : "l"(p));
    return a;
}

#define LDSM4(r, addr) \
    asm volatile("ldmatrix.sync.aligned.m8n8.x4.shared.b16 {%0,%1,%2,%3}, [%4];" \
        : "=r"((r)[0]), "=r"((r)[1]), "=r"((r)[2]), "=r"((r)[3]) : "r"(addr))

#define MMA(acc, a, b0, b1) \
    asm volatile("mma.sync.aligned.m16n8k16.row.col.f32.bf16.bf16.f32 " \
        "{%0,%1,%2,%3}, {%4,%5,%6,%7}, {%8,%9}, {%0,%1,%2,%3};" \
        : "+f"((acc)[0]), "+f"((acc)[1]), "+f"((acc)[2]), "+f"((acc)[3]) \
        : "r"((a)[0]), "r"((a)[1]), "r"((a)[2]), "r"((a)[3]), "r"(b0), "r"(b1))

__device__ __forceinline__ float2 bf2f(uint32_t u) {
    __nv_bfloat162 b = *reinterpret_cast<__nv_bfloat162*>(&u);
    return __bfloat1622float2(b);
}

// Stage: A-combined tile (128 rows x [hi 64B | lo 64B]) 16KB + B-combined 16KB
#define STAGE_BYTES 32768
#define NSTAGE 3
#define SMEM_BYTES (NSTAGE * STAGE_BYTES)   // 96 KB; epilogue fp32 [128][129] = 66 KB overlays

// ---------------------------------------------------------------------------
// Split-bf16 tensor-core GEMM via mma.sync:
// D[m,n] = sum_k A[m,k]*B[n,k]  (both operands K-major)
// CTA 128x128, BK=32, 3-stage cp.async pipeline, 2 CTAs/SM.
// Single __syncthreads per chunk: wait -> sync -> compute -> issue loads(i+2).
// A-fragments double-buffered across im; MMA passes grouped hh/hl/lh.
// EPI 0: bf16 hi/lo TRANSPOSED store out[n][m], + bias[m]
// EPI 1: fp32 TRANSPOSED store, * rsqrt(max(rs[m]*cs[n], eps))
// EPI 2: fp32 direct store out[m][n]
// ---------------------------------------------------------------------------
template <int EPI>
__global__ __launch_bounds__(256, 2)
void mma_gemm(const bf16* __restrict__ Ahi, const bf16* __restrict__ Alo, size_t sA,
              const bf16* __restrict__ Bhi, const bf16* __restrict__ Blo, size_t sB,
              float* __restrict__ outF, bf16* __restrict__ oHi, bf16* __restrict__ oLo,
              const float* __restrict__ bias, const float* __restrict__ rs,
              const float* __restrict__ cs)
{
    extern __shared__ char smem[];
    const int tid  = threadIdx.x;
    const int lane = tid & 31, warp = tid >> 5;
    const int wm = (warp >> 2) * 64, wn = (warp & 3) * 32;
    const int bz = blockIdx.z;
    const int bm = blockIdx.y * 128, bn = blockIdx.x * 128;
    const uint32_t sbase = smem_to_u32(smem);

    const bf16* pAh = Ahi + (size_t)bz * sA + (size_t)bm * DIM;
    const bf16* pAl = Alo + (size_t)bz * sA + (size_t)bm * DIM;
    const bf16* pBh = Bhi + (size_t)bz * sB + (size_t)bn * DIM;
    const bf16* pBl = Blo + (size_t)bz * sB + (size_t)bn * DIM;

    // combined tile: 128 rows x 128B; chunks c<4 = hi k[0..31], c>=4 = lo k[0..31]
    auto load_combined = [&](uint32_t dst, const bf16* hi, const bf16* lo, int kc) {
        #pragma unroll
        for (int i = 0; i < 4; i++) {
            int cid = tid + i * 256;          // 0..1023
            int r = cid >> 3, c = cid & 7;
            const bf16* src = (c < 4) ? (hi + (size_t)r * DIM + kc + c * 8)
                                      : (lo + (size_t)r * DIM + kc + (c - 4) * 8);
            uint32_t p = (uint32_t)(c ^ (r & 7));
            asm volatile("cp.async.cg.shared.global [%0], [%1], 16;"
                         :: "r"(dst + (uint32_t)(r * 128 + p * 16)), "l"(src));
        }
    };
    auto load_stage = [&](int s, int kc) {
        uint32_t st = sbase + (uint32_t)s * STAGE_BYTES;
        load_combined(st,         pAh, pAl, kc);
        load_combined(st + 16384, pBh, pBl, kc);
        asm volatile("cp.async.commit_group;" ::: "memory");
    };

    float acc[4][4][4];
    #pragma unroll
    for (int a = 0; a < 4; a++)
        #pragma unroll
        for (int b = 0; b < 4; b++)
            #pragma unroll
            for (int c = 0; c < 4; c++)
                acc[a][b][c] = 0.0f;

    load_stage(0, 0);
    load_stage(1, 32);

    const int NCHUNK = 32;   // K / 32
    for (int i = 0; i < NCHUNK; i++) {
        if (i + 1 < NCHUNK) {
            asm volatile("cp.async.wait_group 1;" ::: "memory");
        } else {
            asm volatile("cp.async.wait_group 0;" ::: "memory");
        }
        __syncthreads();   // stage i visible to all; all warps done with chunk i-1

        const uint32_t Ab = sbase + (uint32_t)(i % NSTAGE) * STAGE_BYTES;
        const uint32_t Bb = Ab + 16384;

        #pragma unroll
        for (int kk = 0; kk < 2; kk++) {
            uint32_t bh[8], bl[8];
            const int brow = wn + ((lane >> 4) << 3) + (lane & 7);
            const uint32_t bc = (uint32_t)(kk * 2 + ((lane >> 3) & 1));
            #pragma unroll
            for (int g = 0; g < 2; g++) {
                int r = brow + g * 16;
                uint32_t ph = (bc ^ (uint32_t)(r & 7));
                uint32_t pl = ((bc + 4) ^ (uint32_t)(r & 7));
                LDSM4(&bh[g * 4], Bb + (uint32_t)(r * 128) + ph * 16);
                LDSM4(&bl[g * 4], Bb + (uint32_t)(r * 128) + pl * 16);
            }
            const int arow = wm + (lane & 15);
            const uint32_t ac = (uint32_t)(kk * 2 + (lane >> 4));
            uint32_t ah[2][4], al[2][4];
            {
                int r = arow;
                uint32_t ph = (ac ^ (uint32_t)(r & 7));
                uint32_t pl = ((ac + 4) ^ (uint32_t)(r & 7));
                LDSM4(ah[0], Ab + (uint32_t)(r * 128) + ph * 16);
                LDSM4(al[0], Ab + (uint32_t)(r * 128) + pl * 16);
            }
            #pragma unroll
            for (int im = 0; im < 4; im++) {
                const int cur = im & 1, nxt = cur ^ 1;
                if (im < 3) {
                    int r = arow + (im + 1) * 16;
                    uint32_t ph = (ac ^ (uint32_t)(r & 7));
                    uint32_t pl = ((ac + 4) ^ (uint32_t)(r & 7));
                    LDSM4(ah[nxt], Ab + (uint32_t)(r * 128) + ph * 16);
                    LDSM4(al[nxt], Ab + (uint32_t)(r * 128) + pl * 16);
                }
                #pragma unroll
                for (int jn = 0; jn < 4; jn++)
                    MMA(acc[im][jn], ah[cur], bh[2 * jn], bh[2 * jn + 1]);
                #pragma unroll
                for (int jn = 0; jn < 4; jn++)
                    MMA(acc[im][jn], ah[cur], bl[2 * jn], bl[2 * jn + 1]);
                #pragma unroll
                for (int jn = 0; jn < 4; jn++)
                    MMA(acc[im][jn], al[cur], bh[2 * jn], bh[2 * jn + 1]);
            }
        }

        // issue next loads AFTER compute: single-barrier-safe (targets stage (i+2)%3,
        // readers of that stage finished before this chunk's barrier)
        if (i + 2 < NCHUNK)
            load_stage((i + 2) % NSTAGE, (i + 2) * 32);
    }
    __syncthreads();   // protect smem reuse by epilogue

    // ---- epilogue: stage through padded fp32 smem for coalesced stores ----
    float* sfl = (float*)smem;   // [128][129] = 66048 B < SMEM_BYTES
    #pragma unroll
    for (int im = 0; im < 4; im++)
        #pragma unroll
        for (int jn = 0; jn < 4; jn++) {
            int m  = wm + im * 16 + (lane >> 2);
            int nn = wn + jn * 8 + 2 * (lane & 3);
            sfl[m * 129 + nn]           = acc[im][jn][0];
            sfl[m * 129 + nn + 1]       = acc[im][jn][1];
            sfl[(m + 8) * 129 + nn]     = acc[im][jn][2];
            sfl[(m + 8) * 129 + nn + 1] = acc[im][jn][3];
        }
    __syncthreads();

    const size_t obase = (size_t)bz * (size_t)(DIM * DIM);
    if (EPI == 0) {
        const float bv = bias[bm + (tid & 127)];
        #pragma unroll 1
        for (int idx = tid; idx < 128 * 128; idx += 256) {
            int nn = idx >> 7, m = idx & 127;
            float v = sfl[m * 129 + nn] + bv;
            bf16 h = __float2bfloat16(v);
            bf16 l = __float2bfloat16(v - __bfloat162float(h));
            size_t o = obase + (size_t)(bn + nn) * DIM + bm + m;
            oHi[o] = h; oLo[o] = l;
        }
    } else if (EPI == 1) {
        const float rv = rs[bz * DIM + bm + (tid & 127)];
        #pragma unroll 1
        for (int idx = tid; idx < 128 * 128; idx += 256) {
            int nn = idx >> 7, m = idx & 127;
            float v = sfl[m * 129 + nn];
            float sc = rsqrtf(fmaxf(rv * cs[bz * DIM + bn + nn], EPSF));
            outF[obase + (size_t)(bn + nn) * DIM + bm + m] = v * sc;
        }
    } else {
        #pragma unroll 1
        for (int idx = tid; idx < 128 * 128; idx += 256) {
            int m = idx >> 7, nn = idx & 127;
            outF[obase + (size_t)(bm + m) * DIM + bn + nn] = sfl[m * 129 + nn];
        }
    }
}

// ---------------------------------------------------------------------------
// Elementwise kernels
// ---------------------------------------------------------------------------
__global__ __launch_bounds__(256)
void w_split(const float* __restrict__ Wk, const float* __restrict__ Wq)
{
    int i = blockIdx.x * 256 + threadIdx.x;
    float a = Wk[i];
    bf16 h = __float2bfloat16(a);
    g_Wk_hi[i] = h; g_Wk_lo[i] = __float2bfloat16(a - __bfloat162float(h));
    float b = Wq[i];
    h = __float2bfloat16(b);
    g_Wq_hi[i] = h; g_Wq_lo[i] = __float2bfloat16(b - __bfloat162float(h));
}

// X[n][d][b] -> X_hi/lo (same layout) + XT_hi/lo [n][b][d]
__global__ __launch_bounds__(256)
void xprep(const float* __restrict__ X)
{
    __shared__ float t[32][33];
    const int n = blockIdx.z, b0 = blockIdx.x * 32, d0 = blockIdx.y * 32;
    const int tx = threadIdx.x, ty = threadIdx.y;
    const size_t base = (size_t)n << 20;
    const float* Xn = X + base;
    #pragma unroll
    for (int r = 0; r < 4; r++) {
        int row = ty + r * 8;
        float v = Xn[(size_t)(d0 + row) * DIM + b0 + tx];
        t[row][tx] = v;
        bf16 h = __float2bfloat16(v);
        size_t o = base + (size_t)(d0 + row) * DIM + b0 + tx;
        g_X_hi[o] = h; g_X_lo[o] = __float2bfloat16(v - __bfloat162float(h));
    }
    __syncthreads();
    #pragma unroll
    for (int r = 0; r < 4; r++) {
        int row = ty + r * 8;
        float v = t[tx][row];                    // = X[d0+tx][b0+row]
        bf16 h = __float2bfloat16(v);
        size_t o = base + (size_t)(b0 + row) * DIM + d0 + tx;
        g_XT_hi[o] = h; g_XT_lo[o] = __float2bfloat16(v - __bfloat162float(h));
    }
}

// DK2[n,b] = sum_c K[n,c,b]^2 from KT rows (hi+lo); same for Q. one warp/row.
__global__ __launch_bounds__(256)
void norms_k()
{
    const int gw  = (blockIdx.x * 256 + threadIdx.x) >> 5;
    const int lid = threadIdx.x & 31;
    const size_t rb = (size_t)gw << 10;
    const bf16 *kh = g_KT_hi + rb, *kl = g_KT_lo + rb;
    const bf16 *qh = g_QT_hi + rb, *ql = g_QT_lo + rb;
    float sk = 0.f, sq = 0.f;
    #pragma unroll
    for (int c = 0; c < 4; c++) {
        int off = c * 256 + lid * 8;
        uint4 vh = *(const uint4*)(kh + off);
        uint4 vl = *(const uint4*)(kl + off);
        uint4 wh = *(const uint4*)(qh + off);
        uint4 wl = *(const uint4*)(ql + off);
        const uint32_t* ph = (const uint32_t*)&vh;
        const uint32_t* pl = (const uint32_t*)&vl;
        const uint32_t* rh = (const uint32_t*)&wh;
        const uint32_t* rl = (const uint32_t*)&wl;
        #pragma unroll
        for (int u = 0; u < 4; u++) {
            float2 a = bf2f(ph[u]), b = bf2f(pl[u]);
            float x0 = a.x + b.x, x1 = a.y + b.y;
            sk = fmaf(x0, x0, sk); sk = fmaf(x1, x1, sk);
            float2 cq = bf2f(rh[u]), dq = bf2f(rl[u]);
            x0 = cq.x + dq.x; x1 = cq.y + dq.y;
            sq = fmaf(x0, x0, sq); sq = fmaf(x1, x1, sq);
        }
    }
    #pragma unroll
    for (int o = 16; o > 0; o >>= 1) {
        sk += __shfl_xor_sync(0xFFFFFFFFu, sk, o);
        sq += __shfl_xor_sync(0xFFFFFFFFu, sq, o);
    }
    if (lid == 0) { g_DK2[gw] = sk; g_DQ2[gw] = sq; }
}

// Row softmax of YT (each row = one softmax column of Y), write SM hi/lo bf16.
__global__ __launch_bounds__(256)
void softmax_k()
{
    const int row = blockIdx.x;
    const int tid = threadIdx.x;
    float* y = g_YT + ((size_t)row << 10);
    float v[4];
    #pragma unroll
    for (int j = 0; j < 4; j++) v[j] = y[tid + j * 256];
    float m = fmaxf(fmaxf(v[0], v[1]), fmaxf(v[2], v[3]));
    __shared__ float red[8];
    #pragma unroll
    for (int o = 16; o > 0; o >>= 1) m = fmaxf(m, __shfl_xor_sync(0xFFFFFFFFu, m, o));
    if ((tid & 31) == 0) red[tid >> 5] = m;
    __syncthreads();
    float mall = red[0];
    #pragma unroll
    for (int w = 1; w < 8; w++) mall = fmaxf(mall, red[w]);
    float s = 0.f;
    #pragma unroll
    for (int j = 0; j < 4; j++) { v[j] = __expf(v[j] - mall); s += v[j]; }
    #pragma unroll
    for (int o = 16; o > 0; o >>= 1) s += __shfl_xor_sync(0xFFFFFFFFu, s, o);
    __syncthreads();
    if ((tid & 31) == 0) red[tid >> 5] = s;
    __syncthreads();
    float st = 0.f;
    #pragma unroll
    for (int w = 0; w < 8; w++) st += red[w];
    const float inv = 1.0f / st;
    #pragma unroll
    for (int j = 0; j < 4; j++) {
        float p = v[j] * inv;
        bf16 h = __float2bfloat16(p);
        size_t o = ((size_t)row << 10) + tid + j * 256;
        g_SM_hi[o] = h;
        g_SM_lo[o] = __float2bfloat16(p - __bfloat162float(h));
    }
}

// ---------------------------------------------------------------------------
extern "C" void kernel_launch(void* const* d_in, const int* in_sizes, int n_in,
                              void* d_out, int out_size)
{
    const float* X   = (const float*)d_in[0];
    const float* Wk  = (const float*)d_in[1];
    const float* Wq  = (const float*)d_in[2];
    const float* Wk0 = (const float*)d_in[3];
    const float* Wq0 = (const float*)d_in[4];
    float* Z = (float*)d_out;

    cudaFuncSetAttribute(mma_gemm<0>, cudaFuncAttributeMaxDynamicSharedMemorySize, SMEM_BYTES);
    cudaFuncSetAttribute(mma_gemm<1>, cudaFuncAttributeMaxDynamicSharedMemorySize, SMEM_BYTES);
    cudaFuncSetAttribute(mma_gemm<2>, cudaFuncAttributeMaxDynamicSharedMemorySize, SMEM_BYTES);

    bf16 *Wkh, *Wkl, *Wqh, *Wql, *Xh, *Xl, *XTh, *XTl, *KTh, *KTl, *QTh, *QTl, *SMh, *SMl;
    float *YT, *dk2, *dq2;
    cudaGetSymbolAddress((void**)&Wkh, g_Wk_hi);  cudaGetSymbolAddress((void**)&Wkl, g_Wk_lo);
    cudaGetSymbolAddress((void**)&Wqh, g_Wq_hi);  cudaGetSymbolAddress((void**)&Wql, g_Wq_lo);
    cudaGetSymbolAddress((void**)&Xh,  g_X_hi);   cudaGetSymbolAddress((void**)&Xl,  g_X_lo);
    cudaGetSymbolAddress((void**)&XTh, g_XT_hi);  cudaGetSymbolAddress((void**)&XTl, g_XT_lo);
    cudaGetSymbolAddress((void**)&KTh, g_KT_hi);  cudaGetSymbolAddress((void**)&KTl, g_KT_lo);
    cudaGetSymbolAddress((void**)&QTh, g_QT_hi);  cudaGetSymbolAddress((void**)&QTl, g_QT_lo);
    cudaGetSymbolAddress((void**)&SMh, g_SM_hi);  cudaGetSymbolAddress((void**)&SMl, g_SM_lo);
    cudaGetSymbolAddress((void**)&YT,  g_YT);
    cudaGetSymbolAddress((void**)&dk2, g_DK2);    cudaGetSymbolAddress((void**)&dq2, g_DQ2);

    const size_t S = (size_t)DIM * DIM;
    dim3 gg(8, 8, NB);

    w_split<<<(DIM * DIM) / 256, 256>>>(Wk, Wq);
    xprep<<<dim3(32, 32, NB), dim3(32, 8)>>>(X);

    // KT[b,c] = (Wk @ X)^T + Wk0 ; QT likewise (bf16 split, transposed store)
    mma_gemm<0><<<gg, 256, SMEM_BYTES>>>(Wkh, Wkl, 0, XTh, XTl, S,
                                         nullptr, KTh, KTl, Wk0, nullptr, nullptr);
    mma_gemm<0><<<gg, 256, SMEM_BYTES>>>(Wqh, Wql, 0, XTh, XTl, S,
                                         nullptr, QTh, QTl, Wq0, nullptr, nullptr);
    norms_k<<<(NB * DIM) / 8, 256>>>();

    // YT[k,q] = (Q^T K)[q,k] * rsqrt(max(DQ2[q]*DK2[k], eps))
    mma_gemm<1><<<gg, 256, SMEM_BYTES>>>(QTh, QTl, S, KTh, KTl, S,
                                         YT, nullptr, nullptr, nullptr, dq2, dk2);
    softmax_k<<<NB * DIM, 256>>>();

    // Z[c,q] = X @ SM (SM rows are already the K-major B operand)
    mma_gemm<2><<<gg, 256, SMEM_BYTES>>>(Xh, Xl, S, SMh, SMl, S,
                                         Z, nullptr, nullptr, nullptr, nullptr, nullptr);
}